// round 15
// baseline (speedup 1.0000x reference)
#include <cuda_runtime.h>
#include <math.h>
#include <stdint.h>

#define B_  32
#define T_  1024
#define D_  256
#define U_  512
#define G3  1536          // 3*U
#define NCTA_SCAN 128
#define NGRP 2            // 2 independent batch groups
#define GCTA 64           // CTAs per group
#define GB   16           // batches per group
#define NSTEP (T_ + 2)    // pipelined fused steps
#define NTHR 512          // threads per scan CTA (16 warps: 4 quads x 4 col-quarters)
// dynamic SMEM: 3 weight matrices x 24 cols x 512 k
#define WS_BYTES (3 * 24 * U_ * 4)   // 147456

typedef unsigned long long ull;

// packed fp32x2 FMA: d = a*b + d (elementwise on the two fp32 halves)
#define FMA2(d_, a_, b_) \
    asm("fma.rn.f32x2 %0, %1, %2, %3;" : "=l"(d_) : "l"(a_), "l"(b_), "l"(d_))
// splat a scalar float into both halves of a 64-bit packed reg
#define SPLAT2(d_, s_) \
    asm("mov.b64 %0, {%1, %1};" : "=l"(d_) : "r"(__float_as_uint(s_)))

// fast sigmoid / tanh via MUFU.EX2 + MUFU.RCP (~1-2e-7 rel err)
__device__ __forceinline__ float fsig(float x) {
    float e, r;
    asm("ex2.approx.f32 %0, %1;" : "=f"(e) : "f"(x * -1.442695041f));
    asm("rcp.approx.f32 %0, %1;" : "=f"(r) : "f"(1.0f + e));
    return r;
}
__device__ __forceinline__ float ftanh(float x) {
    float e, r;
    asm("ex2.approx.f32 %0, %1;" : "=f"(e) : "f"(x * -2.885390082f));
    asm("rcp.approx.f32 %0, %1;" : "=f"(r) : "f"(1.0f + e));
    return fmaf(2.0f, r, -1.0f);
}

// ---------------- scratch (device globals: allocation-free contract) ----------
__device__ float g_xw[(size_t)T_ * B_ * G3];     // [T,B,3U] layer-0 gate pre-acts
__device__ float g_out0[(size_t)T_ * B_ * U_];   // layer-0 outputs [T,B,U]
__device__ float g_pred0[(size_t)T_ * B_ * U_];  // layer-1 outputs
__device__ float g_pred1[(size_t)T_ * B_ * U_];  // layer-2 outputs
__device__ float g_h[3][2][B_ * U_];             // per-layer double-buffered h
__device__ unsigned g_bar_count[NGRP * 32];      // per-group, 128B apart
__device__ volatile unsigned g_bar_gen[NGRP * 32];

// ---------------- per-group barrier (R10/R14-proven) ---------------------------
__device__ __forceinline__ void group_barrier(int grp, unsigned target) {
    __syncthreads();
    if (threadIdx.x == 0) {
        __threadfence();                           // release all prior stores
        unsigned arrived = atomicAdd(&g_bar_count[grp * 32], 1u);
        if (arrived == GCTA - 1u) {
            g_bar_count[grp * 32] = 0;
            __threadfence();
            g_bar_gen[grp * 32] = target;          // release group's spinners
        } else {
            while (g_bar_gen[grp * 32] < target) { }
        }
        __threadfence();                           // acquire
    }
    __syncthreads();
}

// ---------------- one mat-vec pass: acc[4][6] over 512 k ----------------------
// wsp: warp's 6 weight cols [c][512] in SMEM (c = g*2 + j, g gate, j unit pair
// index). vA (optional vB scaled by a0p): input vectors, stride U_, base b0.
// Act lanes (l<8: lb=l>>1 batch, uj=l&1 unit) receive S[0..2] = (z,r,h) sums.
template<bool DUAL>
__device__ __forceinline__ void pass_mv(
    const float* __restrict__ wsp,
    const float* __restrict__ vA,
    const float* __restrict__ vB,
    ull a0p, int l,
    unsigned bit0, unsigned bit1, unsigned bit2,
    float* __restrict__ S)
{
    ull acc[4][6];
    #pragma unroll
    for (int b = 0; b < 4; b++)
        #pragma unroll
        for (int c = 0; c < 6; c++) acc[b][c] = 0ull;

    #pragma unroll
    for (int i2 = 0; i2 < 4; i2++) {
        const int ko = 4 * l + 128 * i2;
        ulonglong2 hq[4];
        #pragma unroll
        for (int b = 0; b < 4; b++) {
            hq[b] = __ldcg((const ulonglong2*)(vA + b * U_ + ko));
            if (DUAL) {
                ulonglong2 pq = __ldcg((const ulonglong2*)(vB + b * U_ + ko));
                FMA2(hq[b].x, pq.x, a0p);          // hq = vA + a0*vB
                FMA2(hq[b].y, pq.y, a0p);
            }
        }
        #pragma unroll
        for (int c = 0; c < 6; c++) {
            ulonglong2 wq = *(const ulonglong2*)(wsp + c * U_ + ko);
            #pragma unroll
            for (int b = 0; b < 4; b++) {
                FMA2(acc[b][c], hq[b].x, wq.x);
                FMA2(acc[b][c], hq[b].y, wq.y);
            }
        }
    }

    float A[4][6];
    #pragma unroll
    for (int b = 0; b < 4; b++)
        #pragma unroll
        for (int c = 0; c < 6; c++) {
            float2 v = *reinterpret_cast<float2*>(&acc[b][c]);
            A[b][c] = v.x + v.y;
        }

    // butterfly over 24 slots: fold s16, fold s8, then compact lbH/lbL/uj
    #pragma unroll
    for (int b = 0; b < 4; b++)
        #pragma unroll
        for (int c = 0; c < 6; c++) {
            A[b][c] += __shfl_xor_sync(0xffffffffu, A[b][c], 16);
            A[b][c] += __shfl_xor_sync(0xffffffffu, A[b][c], 8);
        }
    // s=4: keep batch-high == bit2 -> 12 slots
    float B4[2][6];
    #pragma unroll
    for (int b2 = 0; b2 < 2; b2++)
        #pragma unroll
        for (int c = 0; c < 6; c++) {
            float keep = bit2 ? A[2 + b2][c] : A[b2][c];
            float send = bit2 ? A[b2][c]     : A[2 + b2][c];
            B4[b2][c] = keep + __shfl_xor_sync(0xffffffffu, send, 4);
        }
    // s=2: keep batch-low == bit1 -> 6 slots
    float B2[6];
    #pragma unroll
    for (int c = 0; c < 6; c++) {
        float keep = bit1 ? B4[1][c] : B4[0][c];
        float send = bit1 ? B4[0][c] : B4[1][c];
        B2[c] = keep + __shfl_xor_sync(0xffffffffu, send, 2);
    }
    // s=1: keep unit j == bit0 -> 3 slots (z, r, h)
    #pragma unroll
    for (int g = 0; g < 3; g++) {
        float keep = bit0 ? B2[g * 2 + 1] : B2[g * 2];
        float send = bit0 ? B2[g * 2]     : B2[g * 2 + 1];
        S[g] = keep + __shfl_xor_sync(0xffffffffu, send, 1);
    }
}

// ---------------- fused 3-layer pipelined GRU scan (512 threads) --------------
// 2 groups x 64 CTAs; CTA owns 8 units x 16 batches for all 3 layers.
// 16 warps: w = q*4+cq; q = batch quad (4 batches), cq = col quarter (2 units).
__global__ void __launch_bounds__(NTHR, 1) scan_kernel(
    const float* __restrict__ r0,
    const float* __restrict__ ks,
    const float* __restrict__ rs,
    const float* __restrict__ b0rec,
    const float* __restrict__ bsin,
    const float* __restrict__ bsrec,
    const float* __restrict__ h00,
    const float* __restrict__ h01,
    const float* __restrict__ h02,
    const float* __restrict__ avec)
{
    extern __shared__ float ws[];     // [3 matrices][24 cols][512 k]

    const int tid = threadIdx.x;
    const int grp = blockIdx.x >> 6;          // 0..1
    const int cic = blockIdx.x & 63;          // CTA within group
    const int u0  = cic * 8;                  // first unit owned
    const int bbase = grp * GB;               // first batch of group

    // Preload 3 weight matrices' 24-col shares.
    // col layout: c = (uo>>1)*6 + g*2 + (uo&1)  (quarter-major, gate pairs)
    #pragma unroll
    for (int m = 0; m < 3; m++) {
        const float* W = (m == 0) ? r0 : (m == 1) ? ks : rs;
        float* wsm = ws + m * 24 * U_;
        for (int idx = tid; idx < 24 * U_; idx += NTHR) {
            int uo = idx & 7;
            int g  = (idx >> 3) % 3;
            int k  = idx / 24;
            int c  = (uo >> 1) * 6 + g * 2 + (uo & 1);
            wsm[c * U_ + k] = W[(size_t)k * G3 + g * U_ + u0 + uo];
        }
    }
    // h init (parity-0 buffers): CTA writes its 16b x 8u slice of each layer.
    if (tid < 128) {
        int b = tid >> 3, uo = tid & 7;
        int i = (bbase + b) * U_ + u0 + uo;
        g_h[0][0][i] = h00[u0 + uo];
        g_h[1][0][i] = h01[u0 + uo];
        g_h[2][0][i] = h02[u0 + uo];
    }

    const int w  = tid >> 5, l = tid & 31;
    const int q  = w >> 2;                    // batch quad 0..3
    const int cq = w & 3;                     // col quarter 0..3 (2 units)
    const int b0 = bbase + q * 4;             // warp's first batch
    const float* ws0 = ws + cq * 6 * U_;                 // r0 share
    const float* wsK = ws + 24 * U_ + cq * 6 * U_;       // ks share
    const float* wsR = ws + 48 * U_ + cq * 6 * U_;       // rs share

    const int lb = l >> 1, uj = l & 1;        // act mapping (l<8)
    const int gb = b0 + lb;                   // batch (act lanes)
    const int gu = u0 + cq * 2 + uj;          // unit (act lanes)
    const bool act = (l < 8);
    const unsigned bit0 = l & 1, bit1 = (l >> 1) & 1, bit2 = (l >> 2) & 1;

    float b0z = 0.f, b0r = 0.f, b0h = 0.f;
    float biz = 0.f, bir = 0.f, bih = 0.f;
    float brz = 0.f, brr = 0.f, brh = 0.f;
    if (act) {
        b0z = b0rec[gu];  b0r = b0rec[U_ + gu];  b0h = b0rec[2 * U_ + gu];
        biz = bsin[gu];   bir = bsin[U_ + gu];   bih = bsin[2 * U_ + gu];
        brz = bsrec[gu];  brr = bsrec[U_ + gu];  brh = bsrec[2 * U_ + gu];
    }
    const float a0 = __ldg(avec);
    ull a0p; SPLAT2(a0p, a0);

    // prefetch layer0 xw for t=0
    float xz0 = 0.f, xr0 = 0.f, xh0 = 0.f;
    if (act) {
        const float* xwt = g_xw + (size_t)gb * G3;
        xz0 = __ldg(xwt + gu);
        xr0 = __ldg(xwt + U_ + gu);
        xh0 = __ldg(xwt + 2 * U_ + gu);
    }

    group_barrier(grp, 1u);   // weights + h-init visible group-wide

    for (int s = 0; s < NSTEP; s++) {
        const int t0 = s, t1 = s - 1, t2 = s - 2;
        float S[3], Sx[3];

        // ---- layer 0 @ t0 ----
        if (t0 < T_) {
            const float* hR = g_h[0][t0 & 1];
            float*       hW = g_h[0][(t0 + 1) & 1];
            float hold = act ? __ldcg(hR + gb * U_ + gu) : 0.f;
            pass_mv<false>(ws0, hR + b0 * U_, (const float*)0, a0p, l,
                           bit0, bit1, bit2, S);
            if (act) {
                float z  = fsig(xz0 + S[0] + b0z);
                float r  = fsig(xr0 + S[1] + b0r);
                float hh = ftanh(xh0 + r * (S[2] + b0h));
                float hnew = z * hold + (1.f - z) * hh;
                g_out0[((size_t)t0 * B_ + gb) * U_ + gu] = hnew;
                __stcg(hW + gb * U_ + gu, hnew + 0.1f * (hold - hnew));
            }
            if (act && t0 + 1 < T_) {
                const float* xwt = g_xw + ((size_t)(t0 + 1) * B_ + gb) * G3;
                xz0 = __ldg(xwt + gu);
                xr0 = __ldg(xwt + U_ + gu);
                xh0 = __ldg(xwt + 2 * U_ + gu);
            }
        }

        // ---- layer 1 @ t1 ----
        if (t1 >= 0 && t1 < T_) {
            const float* vin = g_out0 + ((size_t)t1 * B_ + b0) * U_;
            pass_mv<false>(wsK, vin, (const float*)0, a0p, l,
                           bit0, bit1, bit2, Sx);
            const float* hR = g_h[1][t1 & 1];
            float*       hW = g_h[1][(t1 + 1) & 1];
            float hold = act ? __ldcg(hR + gb * U_ + gu) : 0.f;
            pass_mv<false>(wsR, hR + b0 * U_, (const float*)0, a0p, l,
                           bit0, bit1, bit2, S);
            if (act) {
                float z  = fsig((Sx[0] + biz) + S[0] + brz);
                float r  = fsig((Sx[1] + bir) + S[1] + brr);
                float hh = ftanh((Sx[2] + bih) + r * (S[2] + brh));
                float hnew = z * hold + (1.f - z) * hh;
                g_pred0[((size_t)t1 * B_ + gb) * U_ + gu] = hnew;
                __stcg(hW + gb * U_ + gu, hnew + 0.1f * (hold - hnew));
            }
        }

        // ---- layer 2 @ t2 ----
        if (t2 >= 0) {
            const float* vA = g_out0  + ((size_t)t2 * B_ + b0) * U_;
            const float* vB = g_pred0 + ((size_t)t2 * B_ + b0) * U_;
            pass_mv<true>(wsK, vA, vB, a0p, l, bit0, bit1, bit2, Sx);
            const float* hR = g_h[2][t2 & 1];
            float*       hW = g_h[2][(t2 + 1) & 1];
            float hold = act ? __ldcg(hR + gb * U_ + gu) : 0.f;
            pass_mv<false>(wsR, hR + b0 * U_, (const float*)0, a0p, l,
                           bit0, bit1, bit2, S);
            if (act) {
                float z  = fsig((Sx[0] + biz) + S[0] + brz);
                float r  = fsig((Sx[1] + bir) + S[1] + brr);
                float hh = ftanh((Sx[2] + bih) + r * (S[2] + brh));
                float hnew = z * hold + (1.f - z) * hh;
                g_pred1[((size_t)t2 * B_ + gb) * U_ + gu] = hnew;
                __stcg(hW + gb * U_ + gu, hnew + 0.1f * (hold - hnew));
            }
        }

        if (s + 1 < NSTEP) group_barrier(grp, (unsigned)(s + 2));
    }
}

// ---------------- fp32 GEMM: 128x64 tile, 8x4 microtile, reg-staged prefetch --
// C = rowmap(A0 + s1*A1 + s2*A2) @ W + bias. Block (0,0) zeroes barrier state.
__global__ void __launch_bounds__(256) gemm_kernel(
    const float* __restrict__ A0, const float* __restrict__ A1,
    const float* __restrict__ A2, const float* __restrict__ avec,
    int ia1, int ia2,
    const float* __restrict__ W, const float* __restrict__ bias,
    float* __restrict__ C, int M, int N, int K, int permA, int permC)
{
    __shared__ float As[16][132];   // [k][m], +4 pad
    __shared__ float Bs[16][64];

    const int tid = threadIdx.x;
    if (blockIdx.x == 0 && blockIdx.y == 0 && tid < NGRP) {
        g_bar_count[tid * 32] = 0;
        g_bar_gen[tid * 32]   = 0;
    }

    const int bm = blockIdx.x * 128;
    const int bn = blockIdx.y * 64;

    const int ra0 = tid >> 2;
    const int ra1 = ra0 + 64;
    const int ka  = (tid & 3) << 2;
    const int rb = tid >> 4, cb = (tid & 15) << 2;

    const float s1 = A1 ? avec[ia1] : 0.f;
    const float s2 = A2 ? avec[ia2] : 0.f;

    const int m0 = bm + ra0, m1 = bm + ra1;
    const size_t arow0 = permA ? ((size_t)(m0 & 31) * T_ + (m0 >> 5)) : (size_t)m0;
    const size_t arow1 = permA ? ((size_t)(m1 & 31) * T_ + (m1 >> 5)) : (size_t)m1;
    const float* Ap0a = A0 + arow0 * K + ka;
    const float* Ap0b = A0 + arow1 * K + ka;
    const float* Ap1a = A1 ? (A1 + arow0 * K + ka) : (const float*)0;
    const float* Ap1b = A1 ? (A1 + arow1 * K + ka) : (const float*)0;
    const float* Ap2a = A2 ? (A2 + arow0 * K + ka) : (const float*)0;
    const float* Ap2b = A2 ? (A2 + arow1 * K + ka) : (const float*)0;
    const float* Wp   = W + (size_t)rb * N + bn + cb;

    const int tm = (tid >> 4) << 3;
    const int tn = (tid & 15) << 2;

    ull acc2[8][2];
    #pragma unroll
    for (int i = 0; i < 8; i++) { acc2[i][0] = 0ull; acc2[i][1] = 0ull; }

    float4 av0 = *(const float4*)(Ap0a);
    float4 av1 = *(const float4*)(Ap0b);
    if (A1) {
        float4 t0 = *(const float4*)(Ap1a), t1 = *(const float4*)(Ap1b);
        av0.x += s1 * t0.x; av0.y += s1 * t0.y; av0.z += s1 * t0.z; av0.w += s1 * t0.w;
        av1.x += s1 * t1.x; av1.y += s1 * t1.y; av1.z += s1 * t1.z; av1.w += s1 * t1.w;
    }
    if (A2) {
        float4 t0 = *(const float4*)(Ap2a), t1 = *(const float4*)(Ap2b);
        av0.x += s2 * t0.x; av0.y += s2 * t0.y; av0.z += s2 * t0.z; av0.w += s2 * t0.w;
        av1.x += s2 * t1.x; av1.y += s2 * t1.y; av1.z += s2 * t1.z; av1.w += s2 * t1.w;
    }
    float4 bv = *(const float4*)(Wp);

    for (int k0 = 0; ; k0 += 16) {
        As[ka + 0][ra0] = av0.x; As[ka + 1][ra0] = av0.y;
        As[ka + 2][ra0] = av0.z; As[ka + 3][ra0] = av0.w;
        As[ka + 0][ra1] = av1.x; As[ka + 1][ra1] = av1.y;
        As[ka + 2][ra1] = av1.z; As[ka + 3][ra1] = av1.w;
        *(float4*)&Bs[rb][cb] = bv;
        __syncthreads();

        const bool last = (k0 + 16 >= K);
        if (!last) {
            const int kn = k0 + 16;
            av0 = *(const float4*)(Ap0a + kn);
            av1 = *(const float4*)(Ap0b + kn);
            if (A1) {
                float4 t0 = *(const float4*)(Ap1a + kn), t1 = *(const float4*)(Ap1b + kn);
                av0.x += s1 * t0.x; av0.y += s1 * t0.y; av0.z += s1 * t0.z; av0.w += s1 * t0.w;
                av1.x += s1 * t1.x; av1.y += s1 * t1.y; av1.z += s1 * t1.z; av1.w += s1 * t1.w;
            }
            if (A2) {
                float4 t0 = *(const float4*)(Ap2a + kn), t1 = *(const float4*)(Ap2b + kn);
                av0.x += s2 * t0.x; av0.y += s2 * t0.y; av0.z += s2 * t0.z; av0.w += s2 * t0.w;
                av1.x += s2 * t1.x; av1.y += s2 * t1.y; av1.z += s2 * t1.z; av1.w += s2 * t1.w;
            }
            bv = *(const float4*)(Wp + (size_t)kn * N);
        }

        #pragma unroll
        for (int kk = 0; kk < 16; kk++) {
            float4 aA = *(const float4*)&As[kk][tm];
            float4 aB = *(const float4*)&As[kk][tm + 4];
            ulonglong2 b2 = *(const ulonglong2*)&Bs[kk][tn];
            ull s_[8];
            SPLAT2(s_[0], aA.x); SPLAT2(s_[1], aA.y);
            SPLAT2(s_[2], aA.z); SPLAT2(s_[3], aA.w);
            SPLAT2(s_[4], aB.x); SPLAT2(s_[5], aB.y);
            SPLAT2(s_[6], aB.z); SPLAT2(s_[7], aB.w);
            #pragma unroll
            for (int i = 0; i < 8; i++) {
                FMA2(acc2[i][0], s_[i], b2.x);
                FMA2(acc2[i][1], s_[i], b2.y);
            }
        }
        __syncthreads();
        if (last) break;
    }

    #pragma unroll
    for (int i = 0; i < 8; i++) {
        int m = bm + tm + i;
        size_t crow = permC ? ((size_t)(m & 31) * T_ + (m >> 5)) : (size_t)m;
        float* cp = C + crow * N + bn + tn;
        #pragma unroll
        for (int jp = 0; jp < 2; jp++) {
            float2 v = *reinterpret_cast<float2*>(&acc2[i][jp]);
            cp[2 * jp + 0] = v.x + bias[bn + tn + 2 * jp + 0];
            cp[2 * jp + 1] = v.y + bias[bn + tn + 2 * jp + 1];
        }
    }
}

// ---------------- host orchestration -----------------------------------------
extern "C" void kernel_launch(void* const* d_in, const int* in_sizes, int n_in,
                              void* d_out, int out_size)
{
    const float* x   = (const float*)d_in[0];
    const float* k0  = (const float*)d_in[1];
    const float* r0  = (const float*)d_in[2];
    const float* b0  = (const float*)d_in[3];
    const float* ks  = (const float*)d_in[4];
    const float* rs  = (const float*)d_in[5];
    const float* bs  = (const float*)d_in[6];
    const float* h00 = (const float*)d_in[7];
    const float* h01 = (const float*)d_in[8];
    const float* h02 = (const float*)d_in[9];
    const float* a   = (const float*)d_in[10];
    const float* wd  = (const float*)d_in[11];
    const float* bd  = (const float*)d_in[12];

    float *xw, *out0, *p0, *p1;
    cudaGetSymbolAddress((void**)&xw,   g_xw);
    cudaGetSymbolAddress((void**)&out0, g_out0);
    cudaGetSymbolAddress((void**)&p0,   g_pred0);
    cudaGetSymbolAddress((void**)&p1,   g_pred1);

    cudaFuncSetAttribute(scan_kernel,
                         cudaFuncAttributeMaxDynamicSharedMemorySize, WS_BYTES);

    const int M = B_ * T_;
    dim3 gridW(M / 128, G3 / 64);   // 256 x 24
    dim3 gridF(M / 128, D_ / 64);   // 256 x 4

    // ---- layer 0 input projection: xw = x @ k0 + b_in (also zeroes barriers) --
    gemm_kernel<<<gridW, 256>>>(x, 0, 0, a, 0, 0, k0, b0, xw, M, G3, D_, 1, 0);

    // ---- fused 3-layer pipelined scan (produces out0, pred0, pred1) ----------
    scan_kernel<<<NCTA_SCAN, NTHR, WS_BYTES>>>(r0, ks, rs,
                                               b0 + G3, bs, bs + G3,
                                               h00, h01, h02, a);

    // ---- final: (out0 + a[1]*pred0 + a[2]*pred1) @ wd + bd -> [B,T,D] --------
    gemm_kernel<<<gridF, 256>>>(out0, p0, p1, a, 1, 2, wd, bd,
                                (float*)d_out, M, D_, U_, 0, 1);
}

// round 16
// speedup vs baseline: 1.0803x; 1.0803x over previous
#include <cuda_runtime.h>
#include <math.h>
#include <stdint.h>

#define B_  32
#define T_  1024
#define D_  256
#define U_  512
#define G3  1536          // 3*U
#define NCTA_SCAN 128
#define NGRP 2            // 2 independent batch groups
#define GCTA 64           // CTAs per group
#define GB   16           // batches per group
#define NSTEP (T_ + 2)    // pipelined fused steps
// dynamic SMEM: 3 weight matrices (144KB) + double-buffered 32KB staging
#define WS_FLOATS (3 * 24 * U_)
#define HS_FLOATS (GB * U_)                       // 8192 floats = 32KB
#define SMEM_BYTES ((WS_FLOATS + 2 * HS_FLOATS) * 4)   // 212992 B

typedef unsigned long long ull;

// packed fp32x2 FMA: d = a*b + d (elementwise on the two fp32 halves)
#define FMA2(d_, a_, b_) \
    asm("fma.rn.f32x2 %0, %1, %2, %3;" : "=l"(d_) : "l"(a_), "l"(b_), "l"(d_))
// splat a scalar float into both halves of a 64-bit packed reg
#define SPLAT2(d_, s_) \
    asm("mov.b64 %0, {%1, %1};" : "=l"(d_) : "r"(__float_as_uint(s_)))

// fast sigmoid / tanh via MUFU.EX2 + MUFU.RCP (~1-2e-7 rel err)
__device__ __forceinline__ float fsig(float x) {
    float e, r;
    asm("ex2.approx.f32 %0, %1;" : "=f"(e) : "f"(x * -1.442695041f));
    asm("rcp.approx.f32 %0, %1;" : "=f"(r) : "f"(1.0f + e));
    return r;
}
__device__ __forceinline__ float ftanh(float x) {
    float e, r;
    asm("ex2.approx.f32 %0, %1;" : "=f"(e) : "f"(x * -2.885390082f));
    asm("rcp.approx.f32 %0, %1;" : "=f"(r) : "f"(1.0f + e));
    return fmaf(2.0f, r, -1.0f);
}

// ---------------- scratch (device globals: allocation-free contract) ----------
__device__ float g_xw[(size_t)T_ * B_ * G3];     // [T,B,3U] layer-0 gate pre-acts
__device__ float g_out0[(size_t)T_ * B_ * U_];   // layer-0 outputs [T,B,U]
__device__ float g_pred0[(size_t)T_ * B_ * U_];  // layer-1 outputs
__device__ float g_pred1[(size_t)T_ * B_ * U_];  // layer-2 outputs
__device__ float g_h[3][2][B_ * U_];             // per-layer double-buffered h
__device__ unsigned g_bar_count[NGRP * 32];      // per-group, 128B apart
__device__ volatile unsigned g_bar_gen[NGRP * 32];

// ---------------- per-group barrier (R10/R14-proven) ---------------------------
__device__ __forceinline__ void group_barrier(int grp, unsigned target) {
    __syncthreads();
    if (threadIdx.x == 0) {
        __threadfence();                           // release all prior stores
        unsigned arrived = atomicAdd(&g_bar_count[grp * 32], 1u);
        if (arrived == GCTA - 1u) {
            g_bar_count[grp * 32] = 0;
            __threadfence();
            g_bar_gen[grp * 32] = target;          // release group's spinners
        } else {
            while (g_bar_gen[grp * 32] < target) { }
        }
        __threadfence();                           // acquire
    }
    __syncthreads();
}

// ---------------- staging: cooperative coalesced load of group input ----------
// 16 batches x 512 floats = 2048 float4; 256 threads x 8 each (MLP=8).
__device__ __forceinline__ void stage_vec(float* dst, const float* src, int tid) {
    const float4* s4 = (const float4*)src;
    float4* d4 = (float4*)dst;
    #pragma unroll
    for (int j = 0; j < 8; j++)
        d4[tid + 256 * j] = __ldcg(s4 + tid + 256 * j);
}
// dual: dst = srcA + a0*srcB (combined at stage time)
__device__ __forceinline__ void stage_vec2(float* dst, const float* srcA,
                                           const float* srcB, ull a0p, int tid) {
    const ulonglong2* A = (const ulonglong2*)srcA;
    const ulonglong2* Bp = (const ulonglong2*)srcB;
    ulonglong2* d = (ulonglong2*)dst;
    #pragma unroll
    for (int j = 0; j < 8; j++) {
        ulonglong2 a = __ldcg(A + tid + 256 * j);
        ulonglong2 b = __ldcg(Bp + tid + 256 * j);
        FMA2(a.x, b.x, a0p);
        FMA2(a.y, b.y, a0p);
        d[tid + 256 * j] = a;
    }
}

// ---------------- one mat-vec pass over staged SMEM input ---------------------
// wsp: warp's 12 weight cols [c][512]. vA: staged input base for this warp's
// 4 batches (SMEM, stride U_). Act lanes receive S[0..2] = (z,r,h) sums.
__device__ __forceinline__ void pass_mv(
    const float* __restrict__ wsp,
    const float* __restrict__ vA,
    int l, unsigned bit0, unsigned bit1, unsigned bit2, unsigned bit3,
    float* __restrict__ S)
{
    ull acc[4][12];
    #pragma unroll
    for (int b = 0; b < 4; b++)
        #pragma unroll
        for (int c = 0; c < 12; c++) acc[b][c] = 0ull;

    #pragma unroll
    for (int i2 = 0; i2 < 4; i2++) {
        const int ko = 4 * l + 128 * i2;
        ulonglong2 hq[4];
        #pragma unroll
        for (int b = 0; b < 4; b++)
            hq[b] = *(const ulonglong2*)(vA + b * U_ + ko);   // staged LDS.128
        #pragma unroll
        for (int c = 0; c < 12; c++) {
            ulonglong2 wq = *(const ulonglong2*)(wsp + c * U_ + ko);
            #pragma unroll
            for (int b = 0; b < 4; b++) {
                FMA2(acc[b][c], hq[b].x, wq.x);
                FMA2(acc[b][c], hq[b].y, wq.y);
            }
        }
    }

    float A[4][12];
    #pragma unroll
    for (int b = 0; b < 4; b++)
        #pragma unroll
        for (int c = 0; c < 12; c++) {
            float2 v = *reinterpret_cast<float2*>(&acc[b][c]);
            A[b][c] = v.x + v.y;
        }

    // compacted butterfly (verified rounds 4/7-14)
    #pragma unroll
    for (int b = 0; b < 4; b++)
        #pragma unroll
        for (int c = 0; c < 12; c++)
            A[b][c] += __shfl_xor_sync(0xffffffffu, A[b][c], 16);
    float B8[2][12];
    #pragma unroll
    for (int b2 = 0; b2 < 2; b2++)
        #pragma unroll
        for (int c = 0; c < 12; c++) {
            float keep = bit3 ? A[2 + b2][c] : A[b2][c];
            float send = bit3 ? A[b2][c]     : A[2 + b2][c];
            B8[b2][c] = keep + __shfl_xor_sync(0xffffffffu, send, 8);
        }
    float B4[12];
    #pragma unroll
    for (int c = 0; c < 12; c++) {
        float keep = bit2 ? B8[1][c] : B8[0][c];
        float send = bit2 ? B8[0][c] : B8[1][c];
        B4[c] = keep + __shfl_xor_sync(0xffffffffu, send, 4);
    }
    float B2[3][2];
    #pragma unroll
    for (int g = 0; g < 3; g++)
        #pragma unroll
        for (int j = 0; j < 2; j++) {
            float keep = bit1 ? B4[g * 4 + 2 + j] : B4[g * 4 + j];
            float send = bit1 ? B4[g * 4 + j]     : B4[g * 4 + 2 + j];
            B2[g][j] = keep + __shfl_xor_sync(0xffffffffu, send, 2);
        }
    #pragma unroll
    for (int g = 0; g < 3; g++) {
        float keep = bit0 ? B2[g][1] : B2[g][0];
        float send = bit0 ? B2[g][0] : B2[g][1];
        S[g] = keep + __shfl_xor_sync(0xffffffffu, send, 1);
    }
}

// ---------------- fused 3-layer pipelined GRU scan (256 thr + SMEM staging) ---
// 2 groups x 64 CTAs; CTA owns 8 units x 16 batches, all 3 layers.
// 8 warps: w = q*2+ch; q = batch quad, ch = col half (R14-proven layout).
__global__ void __launch_bounds__(256, 1) scan_kernel(
    const float* __restrict__ r0,
    const float* __restrict__ ks,
    const float* __restrict__ rs,
    const float* __restrict__ b0rec,
    const float* __restrict__ bsin,
    const float* __restrict__ bsrec,
    const float* __restrict__ h00,
    const float* __restrict__ h01,
    const float* __restrict__ h02,
    const float* __restrict__ avec)
{
    extern __shared__ float ws[];     // [3 matrices][24 cols][512 k] + 2x staging
    float* hs0 = ws + WS_FLOATS;
    float* hs1 = hs0 + HS_FLOATS;

    const int tid = threadIdx.x;
    const int grp = blockIdx.x >> 6;          // 0..1
    const int cic = blockIdx.x & 63;          // CTA within group
    const int u0  = cic * 8;                  // first unit owned
    const int bbase = grp * GB;               // first batch of group

    // Preload 3 weight matrices' 24-col shares (verbatim R14 mapping).
    #pragma unroll
    for (int m = 0; m < 3; m++) {
        const float* W = (m == 0) ? r0 : (m == 1) ? ks : rs;
        float* wsm = ws + m * 24 * U_;
        for (int idx = tid; idx < 24 * U_; idx += 256) {
            int uo = idx & 7;
            int g  = (idx >> 3) % 3;
            int k  = idx / 24;
            int c  = (uo >> 2) * 12 + g * 4 + (uo & 3);
            wsm[c * U_ + k] = W[(size_t)k * G3 + g * U_ + u0 + uo];
        }
    }
    // h init (parity-0 buffers): CTA writes its 16b x 8u slice of each layer.
    if (tid < 128) {
        int b = tid >> 3, uo = tid & 7;
        int i = (bbase + b) * U_ + u0 + uo;
        g_h[0][0][i] = h00[u0 + uo];
        g_h[1][0][i] = h01[u0 + uo];
        g_h[2][0][i] = h02[u0 + uo];
    }

    const int w  = tid >> 5, l = tid & 31;
    const int q  = w >> 1;                    // batch quad 0..3
    const int ch = w & 1;                     // col half 0..1
    const float* ws0 = ws + ch * 6144;                 // r0 share
    const float* wsK = ws + 24 * U_ + ch * 6144;       // ks share
    const float* wsR = ws + 48 * U_ + ch * 6144;       // rs share

    const int lb = l >> 2, uj = l & 3;
    const int lbl = q * 4 + lb;               // local batch (act lanes)
    const int gb = bbase + lbl;               // global batch
    const int gu = u0 + ch * 4 + uj;          // unit (act lanes)
    const bool act = (l < 16);
    const unsigned bit0 = l & 1, bit1 = (l >> 1) & 1;
    const unsigned bit2 = (l >> 2) & 1, bit3 = (l >> 3) & 1;

    float b0z = 0.f, b0r = 0.f, b0h = 0.f;
    float biz = 0.f, bir = 0.f, bih = 0.f;
    float brz = 0.f, brr = 0.f, brh = 0.f;
    if (act) {
        b0z = b0rec[gu];  b0r = b0rec[U_ + gu];  b0h = b0rec[2 * U_ + gu];
        biz = bsin[gu];   bir = bsin[U_ + gu];   bih = bsin[2 * U_ + gu];
        brz = bsrec[gu];  brr = bsrec[U_ + gu];  brh = bsrec[2 * U_ + gu];
    }
    const float a0 = __ldg(avec);
    ull a0p; SPLAT2(a0p, a0);

    // prefetch layer0 xw for t=0
    float xz0 = 0.f, xr0 = 0.f, xh0 = 0.f;
    if (act) {
        const float* xwt = g_xw + (size_t)gb * G3;
        xz0 = __ldg(xwt + gu);
        xr0 = __ldg(xwt + U_ + gu);
        xh0 = __ldg(xwt + 2 * U_ + gu);
    }

    group_barrier(grp, 1u);   // weights + h-init visible group-wide

    int pb = 0;               // staging parity (uniform across CTA)

    for (int s = 0; s < NSTEP; s++) {
        const int t0 = s, t1 = s - 1, t2 = s - 2;
        float S[3], Sx[3];

        // ---- pass 0: layer 0 recurrent @ t0 ----
        if (t0 < T_) {
            float* hs = pb ? hs1 : hs0;
            stage_vec(hs, g_h[0][t0 & 1] + bbase * U_, tid);
            __syncthreads();
            float hold = act ? hs[lbl * U_ + gu] : 0.f;
            pass_mv(ws0, hs + q * 4 * U_, l, bit0, bit1, bit2, bit3, S);
            if (act) {
                float z  = fsig(xz0 + S[0] + b0z);
                float r  = fsig(xr0 + S[1] + b0r);
                float hh = ftanh(xh0 + r * (S[2] + b0h));
                float hnew = z * hold + (1.f - z) * hh;
                g_out0[((size_t)t0 * B_ + gb) * U_ + gu] = hnew;
                __stcg(g_h[0][(t0 + 1) & 1] + gb * U_ + gu,
                       hnew + 0.1f * (hold - hnew));
            }
            if (act && t0 + 1 < T_) {
                const float* xwt = g_xw + ((size_t)(t0 + 1) * B_ + gb) * G3;
                xz0 = __ldg(xwt + gu);
                xr0 = __ldg(xwt + U_ + gu);
                xh0 = __ldg(xwt + 2 * U_ + gu);
            }
            pb ^= 1;
        }

        // ---- passes 1-2: layer 1 @ t1 (inproj then recurrent) ----
        if (t1 >= 0 && t1 < T_) {
            float* hs = pb ? hs1 : hs0;
            stage_vec(hs, g_out0 + ((size_t)t1 * B_ + bbase) * U_, tid);
            __syncthreads();
            pass_mv(wsK, hs + q * 4 * U_, l, bit0, bit1, bit2, bit3, Sx);
            pb ^= 1;

            hs = pb ? hs1 : hs0;
            stage_vec(hs, g_h[1][t1 & 1] + bbase * U_, tid);
            __syncthreads();
            float hold = act ? hs[lbl * U_ + gu] : 0.f;
            pass_mv(wsR, hs + q * 4 * U_, l, bit0, bit1, bit2, bit3, S);
            if (act) {
                float z  = fsig((Sx[0] + biz) + S[0] + brz);
                float r  = fsig((Sx[1] + bir) + S[1] + brr);
                float hh = ftanh((Sx[2] + bih) + r * (S[2] + brh));
                float hnew = z * hold + (1.f - z) * hh;
                g_pred0[((size_t)t1 * B_ + gb) * U_ + gu] = hnew;
                __stcg(g_h[1][(t1 + 1) & 1] + gb * U_ + gu,
                       hnew + 0.1f * (hold - hnew));
            }
            pb ^= 1;
        }

        // ---- passes 3-4: layer 2 @ t2 (dual inproj then recurrent) ----
        if (t2 >= 0) {
            float* hs = pb ? hs1 : hs0;
            stage_vec2(hs, g_out0  + ((size_t)t2 * B_ + bbase) * U_,
                           g_pred0 + ((size_t)t2 * B_ + bbase) * U_, a0p, tid);
            __syncthreads();
            pass_mv(wsK, hs + q * 4 * U_, l, bit0, bit1, bit2, bit3, Sx);
            pb ^= 1;

            hs = pb ? hs1 : hs0;
            stage_vec(hs, g_h[2][t2 & 1] + bbase * U_, tid);
            __syncthreads();
            float hold = act ? hs[lbl * U_ + gu] : 0.f;
            pass_mv(wsR, hs + q * 4 * U_, l, bit0, bit1, bit2, bit3, S);
            if (act) {
                float z  = fsig((Sx[0] + biz) + S[0] + brz);
                float r  = fsig((Sx[1] + bir) + S[1] + brr);
                float hh = ftanh((Sx[2] + bih) + r * (S[2] + brh));
                float hnew = z * hold + (1.f - z) * hh;
                g_pred1[((size_t)t2 * B_ + gb) * U_ + gu] = hnew;
                __stcg(g_h[2][(t2 + 1) & 1] + gb * U_ + gu,
                       hnew + 0.1f * (hold - hnew));
            }
            pb ^= 1;
        }

        if (s + 1 < NSTEP) group_barrier(grp, (unsigned)(s + 2));
    }
}

// ---------------- fp32 GEMM: 128x64 tile, 8x4 microtile, reg-staged prefetch --
// C = rowmap(A0 + s1*A1 + s2*A2) @ W + bias. Block (0,0) zeroes barrier state.
__global__ void __launch_bounds__(256) gemm_kernel(
    const float* __restrict__ A0, const float* __restrict__ A1,
    const float* __restrict__ A2, const float* __restrict__ avec,
    int ia1, int ia2,
    const float* __restrict__ W, const float* __restrict__ bias,
    float* __restrict__ C, int M, int N, int K, int permA, int permC)
{
    __shared__ float As[16][132];   // [k][m], +4 pad
    __shared__ float Bs[16][64];

    const int tid = threadIdx.x;
    if (blockIdx.x == 0 && blockIdx.y == 0 && tid < NGRP) {
        g_bar_count[tid * 32] = 0;
        g_bar_gen[tid * 32]   = 0;
    }

    const int bm = blockIdx.x * 128;
    const int bn = blockIdx.y * 64;

    const int ra0 = tid >> 2;
    const int ra1 = ra0 + 64;
    const int ka  = (tid & 3) << 2;
    const int rb = tid >> 4, cb = (tid & 15) << 2;

    const float s1 = A1 ? avec[ia1] : 0.f;
    const float s2 = A2 ? avec[ia2] : 0.f;

    const int m0 = bm + ra0, m1 = bm + ra1;
    const size_t arow0 = permA ? ((size_t)(m0 & 31) * T_ + (m0 >> 5)) : (size_t)m0;
    const size_t arow1 = permA ? ((size_t)(m1 & 31) * T_ + (m1 >> 5)) : (size_t)m1;
    const float* Ap0a = A0 + arow0 * K + ka;
    const float* Ap0b = A0 + arow1 * K + ka;
    const float* Ap1a = A1 ? (A1 + arow0 * K + ka) : (const float*)0;
    const float* Ap1b = A1 ? (A1 + arow1 * K + ka) : (const float*)0;
    const float* Ap2a = A2 ? (A2 + arow0 * K + ka) : (const float*)0;
    const float* Ap2b = A2 ? (A2 + arow1 * K + ka) : (const float*)0;
    const float* Wp   = W + (size_t)rb * N + bn + cb;

    const int tm = (tid >> 4) << 3;
    const int tn = (tid & 15) << 2;

    ull acc2[8][2];
    #pragma unroll
    for (int i = 0; i < 8; i++) { acc2[i][0] = 0ull; acc2[i][1] = 0ull; }

    float4 av0 = *(const float4*)(Ap0a);
    float4 av1 = *(const float4*)(Ap0b);
    if (A1) {
        float4 t0 = *(const float4*)(Ap1a), t1 = *(const float4*)(Ap1b);
        av0.x += s1 * t0.x; av0.y += s1 * t0.y; av0.z += s1 * t0.z; av0.w += s1 * t0.w;
        av1.x += s1 * t1.x; av1.y += s1 * t1.y; av1.z += s1 * t1.z; av1.w += s1 * t1.w;
    }
    if (A2) {
        float4 t0 = *(const float4*)(Ap2a), t1 = *(const float4*)(Ap2b);
        av0.x += s2 * t0.x; av0.y += s2 * t0.y; av0.z += s2 * t0.z; av0.w += s2 * t0.w;
        av1.x += s2 * t1.x; av1.y += s2 * t1.y; av1.z += s2 * t1.z; av1.w += s2 * t1.w;
    }
    float4 bv = *(const float4*)(Wp);

    for (int k0 = 0; ; k0 += 16) {
        As[ka + 0][ra0] = av0.x; As[ka + 1][ra0] = av0.y;
        As[ka + 2][ra0] = av0.z; As[ka + 3][ra0] = av0.w;
        As[ka + 0][ra1] = av1.x; As[ka + 1][ra1] = av1.y;
        As[ka + 2][ra1] = av1.z; As[ka + 3][ra1] = av1.w;
        *(float4*)&Bs[rb][cb] = bv;
        __syncthreads();

        const bool last = (k0 + 16 >= K);
        if (!last) {
            const int kn = k0 + 16;
            av0 = *(const float4*)(Ap0a + kn);
            av1 = *(const float4*)(Ap0b + kn);
            if (A1) {
                float4 t0 = *(const float4*)(Ap1a + kn), t1 = *(const float4*)(Ap1b + kn);
                av0.x += s1 * t0.x; av0.y += s1 * t0.y; av0.z += s1 * t0.z; av0.w += s1 * t0.w;
                av1.x += s1 * t1.x; av1.y += s1 * t1.y; av1.z += s1 * t1.z; av1.w += s1 * t1.w;
            }
            if (A2) {
                float4 t0 = *(const float4*)(Ap2a + kn), t1 = *(const float4*)(Ap2b + kn);
                av0.x += s2 * t0.x; av0.y += s2 * t0.y; av0.z += s2 * t0.z; av0.w += s2 * t0.w;
                av1.x += s2 * t1.x; av1.y += s2 * t1.y; av1.z += s2 * t1.z; av1.w += s2 * t1.w;
            }
            bv = *(const float4*)(Wp + (size_t)kn * N);
        }

        #pragma unroll
        for (int kk = 0; kk < 16; kk++) {
            float4 aA = *(const float4*)&As[kk][tm];
            float4 aB = *(const float4*)&As[kk][tm + 4];
            ulonglong2 b2 = *(const ulonglong2*)&Bs[kk][tn];
            ull s_[8];
            SPLAT2(s_[0], aA.x); SPLAT2(s_[1], aA.y);
            SPLAT2(s_[2], aA.z); SPLAT2(s_[3], aA.w);
            SPLAT2(s_[4], aB.x); SPLAT2(s_[5], aB.y);
            SPLAT2(s_[6], aB.z); SPLAT2(s_[7], aB.w);
            #pragma unroll
            for (int i = 0; i < 8; i++) {
                FMA2(acc2[i][0], s_[i], b2.x);
                FMA2(acc2[i][1], s_[i], b2.y);
            }
        }
        __syncthreads();
        if (last) break;
    }

    #pragma unroll
    for (int i = 0; i < 8; i++) {
        int m = bm + tm + i;
        size_t crow = permC ? ((size_t)(m & 31) * T_ + (m >> 5)) : (size_t)m;
        float* cp = C + crow * N + bn + tn;
        #pragma unroll
        for (int jp = 0; jp < 2; jp++) {
            float2 v = *reinterpret_cast<float2*>(&acc2[i][jp]);
            cp[2 * jp + 0] = v.x + bias[bn + tn + 2 * jp + 0];
            cp[2 * jp + 1] = v.y + bias[bn + tn + 2 * jp + 1];
        }
    }
}

// ---------------- host orchestration -----------------------------------------
extern "C" void kernel_launch(void* const* d_in, const int* in_sizes, int n_in,
                              void* d_out, int out_size)
{
    const float* x   = (const float*)d_in[0];
    const float* k0  = (const float*)d_in[1];
    const float* r0  = (const float*)d_in[2];
    const float* b0  = (const float*)d_in[3];
    const float* ks  = (const float*)d_in[4];
    const float* rs  = (const float*)d_in[5];
    const float* bs  = (const float*)d_in[6];
    const float* h00 = (const float*)d_in[7];
    const float* h01 = (const float*)d_in[8];
    const float* h02 = (const float*)d_in[9];
    const float* a   = (const float*)d_in[10];
    const float* wd  = (const float*)d_in[11];
    const float* bd  = (const float*)d_in[12];

    float *xw, *out0, *p0, *p1;
    cudaGetSymbolAddress((void**)&xw,   g_xw);
    cudaGetSymbolAddress((void**)&out0, g_out0);
    cudaGetSymbolAddress((void**)&p0,   g_pred0);
    cudaGetSymbolAddress((void**)&p1,   g_pred1);

    cudaFuncSetAttribute(scan_kernel,
                         cudaFuncAttributeMaxDynamicSharedMemorySize, SMEM_BYTES);

    const int M = B_ * T_;
    dim3 gridW(M / 128, G3 / 64);   // 256 x 24
    dim3 gridF(M / 128, D_ / 64);   // 256 x 4

    // ---- layer 0 input projection: xw = x @ k0 + b_in (also zeroes barriers) --
    gemm_kernel<<<gridW, 256>>>(x, 0, 0, a, 0, 0, k0, b0, xw, M, G3, D_, 1, 0);

    // ---- fused 3-layer pipelined scan (produces out0, pred0, pred1) ----------
    scan_kernel<<<NCTA_SCAN, 256, SMEM_BYTES>>>(r0, ks, rs,
                                                b0 + G3, bs, bs + G3,
                                                h00, h01, h02, a);

    // ---- final: (out0 + a[1]*pred0 + a[2]*pred1) @ wd + bd -> [B,T,D] --------
    gemm_kernel<<<gridF, 256>>>(out0, p0, p1, a, 1, 2, wd, bd,
                                (float*)d_out, M, D_, U_, 0, 1);
}